// round 16
// baseline (speedup 1.0000x reference)
#include <cuda_runtime.h>
#include <cuda_bf16.h>
#include <cstdint>

// RepeatEncoder: LIF spiking neuron over T=32 repeated presentations of the
// same frame. Input [B=64, C=64, L=512] fp32 -> output [B, T=32, L, C] fp32.
//
// Per (b,l,c): x = in[b,c,l]; v=0; for t in 0..31:
//   v += (x - v)*0.5;  s = (v >= 1);  v = s ? 0 : v;  out[b,t,l,c] = s
//
// FINAL (converged over R4-R15): wall time is pinned by the sustained DRAM
// drain of the irreducible 256 MB fp32 output stream at ~6.1 TB/s (HBM3e
// write-mostly effective ceiling; DRAM duty plateaus ~64% for pure-write
// streams due to turnaround/refresh). Exhaustively falsified byte-neutral
// levers: tile sizes LT={16,32,64}, store widths {128b,256b}, cache
// policies {default,.cs,.wt}, grid granularity, 64- vs 32-bit addressing.
// Winning ingredients:
//  - coalesced smem-staged input (8 KB/CTA, 128B per-warp LDGs)
//  - perfectly coalesced float4 stores, 512B contiguous per warp
//  - st.global.cs (evict-first) so dirty-L2 drain overlaps graph replays
//  - LT=32 l-tile, 512-thread CTAs, grid 1024 -> 4 CTAs/SM, 2048 thr/SM
//  - exact arithmetic match to the JAX reference (rel_err == 0.0)

namespace {
constexpr int B  = 64;
constexpr int C  = 64;
constexpr int L  = 512;
constexpr int T  = 32;
constexpr int LT = 32;                 // l-tile per block
constexpr int THREADS = 512;           // = LT * (C/4) compute units
constexpr int PITCH = LT + 1;          // smem pitch (33 floats)
}

__global__ void __launch_bounds__(THREADS)
lif_repeat_encoder_kernel(const float* __restrict__ in, float* __restrict__ out) {
    __shared__ float tile[C * PITCH];  // tile[c][ll], pitch 33

    const int tid = threadIdx.x;
    const int bid = blockIdx.x;        // 0 .. 1023
    const int b   = bid >> 4;          // bid / (L/LT)
    const int l0  = (bid & 15) << 5;   // (bid % 16) * 32

    // ---- Coalesced load: input [B, C, L]; block needs [b, 0:64, l0:l0+32].
    // Each warp loads 32 consecutive floats (128B). 4 rows per thread.
    {
        const int ll = tid & 31;       // l within tile
        const int cr = tid >> 5;       // 0..15
        const float* src = in + ((size_t)b * C) * L + l0 + ll;
        #pragma unroll
        for (int i = 0; i < 4; ++i) {
            const int c = cr + i * 16;
            tile[c * PITCH + ll] = src[(size_t)c * L];
        }
    }
    __syncthreads();

    // ---- Compute + store: thread owns (ll, c4) -> 4 consecutive channels.
    const int c4 = tid & 15;           // channel group 0..15
    const int ll = tid >> 4;           // l within tile 0..31
    const int c  = c4 * 4;
    const int l  = l0 + ll;

    const float x0 = tile[(c + 0) * PITCH + ll];
    const float x1 = tile[(c + 1) * PITCH + ll];
    const float x2 = tile[(c + 2) * PITCH + ll];
    const float x3 = tile[(c + 3) * PITCH + ll];

    float v0 = 0.f, v1 = 0.f, v2 = 0.f, v3 = 0.f;

    // Output [B, T, L, C]: single base pointer; every store addressed as
    // [base + compile-time-constant offset] (offsets < 2^28 bytes).
    const unsigned base_f = ((unsigned)b * T * L + (unsigned)l) * C + (unsigned)c;
    char* const outb = reinterpret_cast<char*>(out) + (size_t)base_f * 4u;
    constexpr unsigned strideT_bytes = (unsigned)L * C * 4u;  // 131072

    #pragma unroll
    for (int t = 0; t < T; ++t) {
        // v = v + (x - v)/tau, tau = 2 (mul by 0.5 is exact)
        v0 += (x0 - v0) * 0.5f;
        v1 += (x1 - v1) * 0.5f;
        v2 += (x2 - v2) * 0.5f;
        v3 += (x3 - v3) * 0.5f;

        const float s0 = (v0 >= 1.0f) ? 1.0f : 0.0f;
        const float s1 = (v1 >= 1.0f) ? 1.0f : 0.0f;
        const float s2 = (v2 >= 1.0f) ? 1.0f : 0.0f;
        const float s3 = (v3 >= 1.0f) ? 1.0f : 0.0f;

        v0 = (s0 != 0.0f) ? 0.0f : v0;
        v1 = (s1 != 0.0f) ? 0.0f : v1;
        v2 = (s2 != 0.0f) ? 0.0f : v2;
        v3 = (s3 != 0.0f) ? 0.0f : v3;

        // Streaming store, evict-first; offset folds into the STG immediate.
        float4* dst = reinterpret_cast<float4*>(outb + (unsigned)t * strideT_bytes);
        __stcs(dst, make_float4(s0, s1, s2, s3));
    }
}

extern "C" void kernel_launch(void* const* d_in, const int* in_sizes, int n_in,
                              void* d_out, int out_size) {
    (void)in_sizes; (void)n_in; (void)out_size;
    const float* in = (const float*)d_in[0];
    float* out = (float*)d_out;

    const int blocks = B * (L / LT);   // 1024
    lif_repeat_encoder_kernel<<<blocks, THREADS>>>(in, out);
}